// round 2
// baseline (speedup 1.0000x reference)
#include <cuda_runtime.h>
#include <cuda_bf16.h>
#include <math.h>

// ---------------- problem constants (fixed by the dataset) ----------------
#define NN   50000      // nodes
#define EE   500000     // edges
#define GG   50         // graphs
#define INF_ 3.402823466e+38f

#define H1D  64         // HID[0]
#define H2D  128        // HID[1]
#define NH   4          // heads
#define SLOPE 0.2f

// ---------------- scratch (device globals; no allocation) ----------------
__device__ float g_fs1[NN * NH * H1D];   // 51.2 MB
__device__ float g_fd1[NN * NH * H1D];
__device__ float g_h1 [NN * H1D];
__device__ float g_fs2[NN * NH * H2D];   // 102.4 MB
__device__ float g_fd2[NN * NH * H2D];
__device__ float g_h2 [NN * H2D];

__device__ int g_deg[NN];
__device__ int g_rs [NN + 1];
__device__ int g_cur[NN];
__device__ int g_adj[EE];       // dst-sorted src list (CSR payload)

// ---------------- CSR build ----------------
__global__ void k_zero_deg() {
    int i = blockIdx.x * blockDim.x + threadIdx.x;
    if (i < NN) g_deg[i] = 0;
}

__global__ void k_hist(const int* __restrict__ dst, int E) {
    int i = blockIdx.x * blockDim.x + threadIdx.x;
    if (i < E) atomicAdd(&g_deg[dst[i]], 1);
}

__global__ void k_scan(int E) {
    __shared__ int sm[1024];
    int tid = threadIdx.x;
    const int chunk = (NN + 1023) / 1024;
    int b = tid * chunk;
    int e = b + chunk; if (e > NN) e = NN;
    int s = 0;
    for (int i = b; i < e; i++) s += g_deg[i];
    sm[tid] = s;
    __syncthreads();
    // Hillis-Steele inclusive scan over 1024 partials
    for (int off = 1; off < 1024; off <<= 1) {
        int v = (tid >= off) ? sm[tid - off] : 0;
        __syncthreads();
        sm[tid] += v;
        __syncthreads();
    }
    int run = sm[tid] - s;   // exclusive prefix for this chunk
    for (int i = b; i < e; i++) {
        g_rs[i] = run;
        g_cur[i] = run;
        run += g_deg[i];
    }
    if (tid == 0) g_rs[NN] = E;
}

__global__ void k_scatter(const int* __restrict__ dst, int E) {
    int i = blockIdx.x * blockDim.x + threadIdx.x;
    if (i < E) {
        int p = atomicAdd(&g_cur[dst[i]], 1);
        g_adj[p] = i;                 // store edge id (sorted next for determinism)
    }
}

__global__ void k_sortseg() {        // per-node insertion sort of edge ids -> deterministic order
    int v = blockIdx.x * blockDim.x + threadIdx.x;
    if (v >= NN) return;
    int s = g_rs[v], e = g_rs[v + 1];
    for (int i = s + 1; i < e; i++) {
        int key = g_adj[i];
        int j = i - 1;
        while (j >= s && g_adj[j] > key) { g_adj[j + 1] = g_adj[j]; j--; }
        g_adj[j + 1] = key;
    }
}

__global__ void k_eid2src(const int* __restrict__ src, int E) {
    int i = blockIdx.x * blockDim.x + threadIdx.x;
    if (i < E) g_adj[i] = src[g_adj[i]];
}

// ---------------- fp32 tiled GEMM + bias: C[N,M] = A[N,K] @ B[K,M] + bias ----------------
// BM=64 BN=64 BK=16, 256 threads, 4x4 microtile
__global__ void k_sgemm_bias(const float* __restrict__ A, const float* __restrict__ B,
                             const float* __restrict__ bias, float* __restrict__ C,
                             int Nrows, int K, int M) {
    __shared__ float As[16][64];   // transposed: As[k][m]
    __shared__ float Bs[16][64];
    const int tid = threadIdx.x;
    const int tx = tid & 15;           // 0..15 (BN/TN)
    const int ty = tid >> 4;           // 0..15 (BM/TM)
    const int row0 = blockIdx.y * 64;
    const int col0 = blockIdx.x * 64;

    // loaders
    const int aRow  = tid >> 2;            // 0..63
    const int aCol4 = (tid & 3) * 4;       // 0,4,8,12
    const int bRow  = tid >> 4;            // 0..15
    const int bCol4 = (tid & 15) * 4;      // 0..60

    float acc[4][4] = {};

    for (int kk = 0; kk < K; kk += 16) {
        float4 av = make_float4(0.f, 0.f, 0.f, 0.f);
        if (row0 + aRow < Nrows)
            av = *(const float4*)(A + (long)(row0 + aRow) * K + kk + aCol4);
        As[aCol4 + 0][aRow] = av.x;
        As[aCol4 + 1][aRow] = av.y;
        As[aCol4 + 2][aRow] = av.z;
        As[aCol4 + 3][aRow] = av.w;
        float4 bv = *(const float4*)(B + (long)(kk + bRow) * M + col0 + bCol4);
        *(float4*)&Bs[bRow][bCol4] = bv;
        __syncthreads();
#pragma unroll
        for (int k = 0; k < 16; k++) {
            float a[4], b[4];
#pragma unroll
            for (int i = 0; i < 4; i++) a[i] = As[k][ty * 4 + i];
#pragma unroll
            for (int j = 0; j < 4; j++) b[j] = Bs[k][tx * 4 + j];
#pragma unroll
            for (int i = 0; i < 4; i++)
#pragma unroll
                for (int j = 0; j < 4; j++) acc[i][j] += a[i] * b[j];
        }
        __syncthreads();
    }
    float4 bb = *(const float4*)(bias + col0 + tx * 4);
    const float bj[4] = { bb.x, bb.y, bb.z, bb.w };
#pragma unroll
    for (int i = 0; i < 4; i++) {
        int r = row0 + ty * 4 + i;
        if (r < Nrows) {
            float4 o;
            o.x = acc[i][0] + bj[0];
            o.y = acc[i][1] + bj[1];
            o.z = acc[i][2] + bj[2];
            o.w = acc[i][3] + bj[3];
            *(float4*)(C + (long)r * M + col0 + tx * 4) = o;
        }
    }
}

// ---------------- fused GATv2 edge-softmax + aggregate + head-maxpool ----------------
// block = 128 threads = 4 warps = 4 heads; grid-stride over nodes
template <int D>
__global__ void k_gat(const float* __restrict__ fs, const float* __restrict__ fd,
                      const float* __restrict__ attn, float* __restrict__ hout) {
    constexpr int VPT = D / 32;
    constexpr int HD = NH * D;
    __shared__ float sh[NH][D];
    const int lane = threadIdx.x & 31;
    const int h = threadIdx.x >> 5;

    float areg[VPT];
#pragma unroll
    for (int i = 0; i < VPT; i++) areg[i] = attn[h * D + i * 32 + lane];

    for (int v = blockIdx.x; v < NN; v += gridDim.x) {
        float fdr[VPT];
        const float* fdp = fd + (long)v * HD + h * D;
#pragma unroll
        for (int i = 0; i < VPT; i++) fdr[i] = fdp[i * 32 + lane];

        const int s0 = g_rs[v], s1 = g_rs[v + 1];
        float m = -INF_, ssum = 0.f;
        float acc[VPT];
#pragma unroll
        for (int i = 0; i < VPT; i++) acc[i] = 0.f;

        for (int idx = s0; idx < s1; idx++) {
            int u = g_adj[idx];
            const float* fsp = fs + (long)u * HD + h * D;
            float fu[VPT];
            float p = 0.f;
#pragma unroll
            for (int i = 0; i < VPT; i++) {
                fu[i] = fsp[i * 32 + lane];
                float t = fu[i] + fdr[i];
                t = t > 0.f ? t : SLOPE * t;
                p += areg[i] * t;
            }
#pragma unroll
            for (int o = 16; o; o >>= 1) p += __shfl_xor_sync(0xffffffffu, p, o);
            float mn = fmaxf(m, p);
            float sc = __expf(m - mn);       // first iter: exp(-inf) = 0
            float pe = __expf(p - mn);
            ssum = ssum * sc + pe;
#pragma unroll
            for (int i = 0; i < VPT; i++) acc[i] = acc[i] * sc + pe * fu[i];
            m = mn;
        }
        float inv = (s1 > s0) ? 1.f / ssum : 0.f;
#pragma unroll
        for (int i = 0; i < VPT; i++) sh[h][i * 32 + lane] = acc[i] * inv;
        __syncthreads();
        for (int d = threadIdx.x; d < D; d += blockDim.x) {
            float mx = fmaxf(fmaxf(sh[0][d], sh[1][d]), fmaxf(sh[2][d], sh[3][d]));
            hout[(long)v * D + d] = mx;
        }
        __syncthreads();
    }
}

// ---------------- global attention pooling: one block (128 thr) per graph ----------------
__global__ void k_pool(const float* __restrict__ gw, const float* __restrict__ gb,
                       float* __restrict__ out, int npg) {
    const int g = blockIdx.x;
    const int tid = threadIdx.x;
    const int lane = tid & 31;
    const int w = tid >> 5;
    extern __shared__ float sg[];        // npg floats
    __shared__ float red[16];
    const int base = g * npg;

    float gwr[4];
#pragma unroll
    for (int i = 0; i < 4; i++) gwr[i] = gw[i * 32 + lane];
    const float gbv = gb[0];

    // phase 1: gate per node (warp per node)
    for (int v = w; v < npg; v += 4) {
        const float* hp = g_h2 + (long)(base + v) * H2D;
        float p = 0.f;
#pragma unroll
        for (int i = 0; i < 4; i++) p += gwr[i] * hp[i * 32 + lane];
#pragma unroll
        for (int o = 16; o; o >>= 1) p += __shfl_xor_sync(0xffffffffu, p, o);
        if (lane == 0) sg[v] = p + gbv;
    }
    __syncthreads();

    // phase 2: softmax over graph
    float mx = -INF_;
    for (int v = tid; v < npg; v += 128) mx = fmaxf(mx, sg[v]);
#pragma unroll
    for (int o = 16; o; o >>= 1) mx = fmaxf(mx, __shfl_xor_sync(0xffffffffu, mx, o));
    if (lane == 0) red[w] = mx;
    __syncthreads();
    if (tid == 0) red[8] = fmaxf(fmaxf(red[0], red[1]), fmaxf(red[2], red[3]));
    __syncthreads();
    const float M = red[8];

    float ss = 0.f;
    for (int v = tid; v < npg; v += 128) {
        float e = __expf(sg[v] - M);
        sg[v] = e;
        ss += e;
    }
#pragma unroll
    for (int o = 16; o; o >>= 1) ss += __shfl_xor_sync(0xffffffffu, ss, o);
    if (lane == 0) red[w] = ss;
    __syncthreads();
    if (tid == 0) red[9] = red[0] + red[1] + red[2] + red[3];
    __syncthreads();
    const float inv = 1.f / red[9];

    // phase 3: weighted sum over nodes, thread = output dim
    float accD = 0.f;
    for (int v = 0; v < npg; v++)
        accD += sg[v] * g_h2[(long)(base + v) * H2D + tid];
    out[g * H2D + tid] = accD * inv;
}

// ---------------- launch ----------------
extern "C" void kernel_launch(void* const* d_in, const int* in_sizes, int n_in,
                              void* d_out, int out_size) {
    const float* x    = (const float*)d_in[0];
    const int* esrc   = (const int*)d_in[1];
    const int* edst   = (const int*)d_in[2];
    // d_in[3] = node_graph (implied by contiguous blocks; unused)
    const float* Wl1  = (const float*)d_in[4];
    const float* bl1  = (const float*)d_in[5];
    const float* Wr1  = (const float*)d_in[6];
    const float* br1  = (const float*)d_in[7];
    const float* at1  = (const float*)d_in[8];
    const float* Wl2  = (const float*)d_in[9];
    const float* bl2  = (const float*)d_in[10];
    const float* Wr2  = (const float*)d_in[11];
    const float* br2  = (const float*)d_in[12];
    const float* at2  = (const float*)d_in[13];
    const float* gw   = (const float*)d_in[14];
    const float* gb   = (const float*)d_in[15];

    const int E = in_sizes[1];
    const int N = in_sizes[0] / 128;
    const int G = out_size / H2D;
    const int npg = N / G;

    float* fs1; float* fd1; float* h1; float* fs2; float* fd2;
    cudaGetSymbolAddress((void**)&fs1, g_fs1);
    cudaGetSymbolAddress((void**)&fd1, g_fd1);
    cudaGetSymbolAddress((void**)&h1,  g_h1);
    cudaGetSymbolAddress((void**)&fs2, g_fs2);
    cudaGetSymbolAddress((void**)&fd2, g_fd2);

    // ---- CSR build (deterministic) ----
    k_zero_deg<<<(NN + 255) / 256, 256>>>();
    k_hist<<<(E + 255) / 256, 256>>>(edst, E);
    k_scan<<<1, 1024>>>(E);
    k_scatter<<<(E + 255) / 256, 256>>>(edst, E);
    k_sortseg<<<(NN + 255) / 256, 256>>>();
    k_eid2src<<<(E + 255) / 256, 256>>>(esrc, E);

    // ---- layer 1 ----
    {
        dim3 grid(NH * H1D / 64, (N + 63) / 64);
        k_sgemm_bias<<<grid, 256>>>(x, Wl1, bl1, fs1, N, 128, NH * H1D);
        k_sgemm_bias<<<grid, 256>>>(x, Wr1, br1, fd1, N, 128, NH * H1D);
    }
    {
        float* ho; cudaGetSymbolAddress((void**)&ho, g_h1);
        k_gat<H1D><<<2368, 128>>>(fs1, fd1, at1, ho);
    }

    // ---- layer 2 ----
    {
        dim3 grid(NH * H2D / 64, (N + 63) / 64);
        k_sgemm_bias<<<grid, 256>>>(h1, Wl2, bl2, fs2, N, H1D, NH * H2D);
        k_sgemm_bias<<<grid, 256>>>(h1, Wr2, br2, fd2, N, H1D, NH * H2D);
    }
    {
        float* ho; cudaGetSymbolAddress((void**)&ho, g_h2);
        k_gat<H2D><<<2368, 128>>>(fs2, fd2, at2, ho);
    }

    // ---- pooling ----
    k_pool<<<G, 128, npg * sizeof(float)>>>(gw, gb, (float*)d_out, npg);
}

// round 3
// speedup vs baseline: 1.0161x; 1.0161x over previous
#include <cuda_runtime.h>
#include <cuda_bf16.h>
#include <math.h>

// ---------------- problem constants (fixed by the dataset) ----------------
#define NN   50000      // nodes
#define EE   500000     // edges
#define GG   50         // graphs
#define INF_ 3.402823466e+38f

#define H1D  64         // HID[0]
#define H2D  128        // HID[1]
#define NH   4          // heads
#define SLOPE 0.2f

// ---------------- scratch (device globals; no allocation) ----------------
__device__ float g_fs1[NN * NH * H1D];   // 51.2 MB
__device__ float g_fd1[NN * NH * H1D];
__device__ float g_h1 [NN * H1D];
__device__ float g_fs2[NN * NH * H2D];   // 102.4 MB
__device__ float g_fd2[NN * NH * H2D];
__device__ float g_h2 [NN * H2D];

__device__ int g_deg[NN];
__device__ int g_rs [NN + 1];
__device__ int g_cur[NN];
__device__ int g_adj[EE];       // dst-sorted src list (CSR payload)

// ---------------- CSR build ----------------
__global__ void k_zero_deg() {
    int i = blockIdx.x * blockDim.x + threadIdx.x;
    if (i < NN) g_deg[i] = 0;
}

__global__ void k_hist(const int* __restrict__ dst, int E) {
    int i = blockIdx.x * blockDim.x + threadIdx.x;
    if (i < E) atomicAdd(&g_deg[dst[i]], 1);
}

__global__ void k_scan(int E) {
    __shared__ int sm[1024];
    int tid = threadIdx.x;
    const int chunk = (NN + 1023) / 1024;
    int b = tid * chunk;
    int e = b + chunk; if (e > NN) e = NN;
    int s = 0;
    for (int i = b; i < e; i++) s += g_deg[i];
    sm[tid] = s;
    __syncthreads();
    for (int off = 1; off < 1024; off <<= 1) {
        int v = (tid >= off) ? sm[tid - off] : 0;
        __syncthreads();
        sm[tid] += v;
        __syncthreads();
    }
    int run = sm[tid] - s;   // exclusive prefix for this chunk
    for (int i = b; i < e; i++) {
        g_rs[i] = run;
        g_cur[i] = run;
        run += g_deg[i];
    }
    if (tid == 0) g_rs[NN] = E;
}

__global__ void k_scatter(const int* __restrict__ dst, int E) {
    int i = blockIdx.x * blockDim.x + threadIdx.x;
    if (i < E) {
        int p = atomicAdd(&g_cur[dst[i]], 1);
        g_adj[p] = i;                 // edge id; sorted next for determinism
    }
}

__global__ void k_sortseg() {        // per-node insertion sort -> deterministic order
    int v = blockIdx.x * blockDim.x + threadIdx.x;
    if (v >= NN) return;
    int s = g_rs[v], e = g_rs[v + 1];
    for (int i = s + 1; i < e; i++) {
        int key = g_adj[i];
        int j = i - 1;
        while (j >= s && g_adj[j] > key) { g_adj[j + 1] = g_adj[j]; j--; }
        g_adj[j + 1] = key;
    }
}

__global__ void k_eid2src(const int* __restrict__ src, int E) {
    int i = blockIdx.x * blockDim.x + threadIdx.x;
    if (i < E) g_adj[i] = src[g_adj[i]];
}

// ---------------- dual-output fp32 GEMM + bias ----------------
// C1[N,M] = A[N,K] @ B1[K,M] + b1 ; C2[N,M] = A[N,K] @ B2[K,M] + b2
// 128x128 block tile, BK=8, 256 threads, 8x8 microtile, double-buffered smem.
// grid.x = 2*(M/128): first half -> output 1, second half -> output 2.
__global__ __launch_bounds__(256)
void k_sgemm_dual(const float* __restrict__ A,
                  const float* __restrict__ B1, const float* __restrict__ b1, float* __restrict__ C1,
                  const float* __restrict__ B2, const float* __restrict__ b2, float* __restrict__ C2,
                  int Nrows, int K, int M) {
    const int nbx = M >> 7;
    int bx = blockIdx.x;
    const float* B = B1; const float* bias = b1; float* C = C1;
    if (bx >= nbx) { bx -= nbx; B = B2; bias = b2; C = C2; }
    const int row0 = blockIdx.y << 7;
    const int col0 = bx << 7;

    __shared__ float As[2][8][128];
    __shared__ float Bs[2][8][128];

    const int tid = threadIdx.x;
    const int tx = tid & 15;           // 16 col groups of 8
    const int ty = tid >> 4;           // 16 row groups of 8

    // loaders: A tile 128x8 (one float4/thread), B tile 8x128 (one float4/thread)
    const int arow = tid >> 1;             // 0..127
    const int acol = (tid & 1) * 4;        // 0 or 4
    const int brow = tid >> 5;             // 0..7
    const int bcol = (tid & 31) * 4;       // 0..124

    const bool aval = (row0 + arow) < Nrows;
    const float* Aptr = A + (long)(row0 + arow) * K + acol;
    const float* Bptr = B + (long)brow * M + col0 + bcol;

    float acc[8][8] = {};

    // stage tile 0
    {
        float4 av = aval ? *(const float4*)Aptr : make_float4(0.f, 0.f, 0.f, 0.f);
        float4 bv = *(const float4*)Bptr;
        As[0][acol + 0][arow] = av.x;
        As[0][acol + 1][arow] = av.y;
        As[0][acol + 2][arow] = av.z;
        As[0][acol + 3][arow] = av.w;
        *(float4*)&Bs[0][brow][bcol] = bv;
    }
    __syncthreads();

    int buf = 0;
    const int ktiles = K >> 3;
    for (int t = 0; t < ktiles; t++) {
        const bool more = (t + 1) < ktiles;
        float4 av2 = make_float4(0.f, 0.f, 0.f, 0.f), bv2;
        if (more) {
            if (aval) av2 = *(const float4*)(Aptr + (t + 1) * 8);
            bv2 = *(const float4*)(Bptr + (long)(t + 1) * 8 * M);
        }
#pragma unroll
        for (int k = 0; k < 8; k++) {
            float a[8], b[8];
            *(float4*)&a[0] = *(const float4*)&As[buf][k][ty * 8];
            *(float4*)&a[4] = *(const float4*)&As[buf][k][ty * 8 + 4];
            *(float4*)&b[0] = *(const float4*)&Bs[buf][k][tx * 8];
            *(float4*)&b[4] = *(const float4*)&Bs[buf][k][tx * 8 + 4];
#pragma unroll
            for (int i = 0; i < 8; i++)
#pragma unroll
                for (int j = 0; j < 8; j++) acc[i][j] += a[i] * b[j];
        }
        if (more) {
            buf ^= 1;
            As[buf][acol + 0][arow] = av2.x;
            As[buf][acol + 1][arow] = av2.y;
            As[buf][acol + 2][arow] = av2.z;
            As[buf][acol + 3][arow] = av2.w;
            *(float4*)&Bs[buf][brow][bcol] = bv2;
            __syncthreads();
        }
    }

    float bj[8];
    *(float4*)&bj[0] = *(const float4*)(bias + col0 + tx * 8);
    *(float4*)&bj[4] = *(const float4*)(bias + col0 + tx * 8 + 4);
#pragma unroll
    for (int i = 0; i < 8; i++) {
        const int r = row0 + ty * 8 + i;
        if (r < Nrows) {
            float4 o0, o1;
            o0.x = acc[i][0] + bj[0]; o0.y = acc[i][1] + bj[1];
            o0.z = acc[i][2] + bj[2]; o0.w = acc[i][3] + bj[3];
            o1.x = acc[i][4] + bj[4]; o1.y = acc[i][5] + bj[5];
            o1.z = acc[i][6] + bj[6]; o1.w = acc[i][7] + bj[7];
            float* cp = C + (long)r * M + col0 + tx * 8;
            *(float4*)cp = o0;
            *(float4*)(cp + 4) = o1;
        }
    }
}

// ---------------- fused GATv2 edge-softmax + aggregate + head-maxpool ----------------
// block = 128 threads = 4 warps = 4 heads; grid-stride over nodes
template <int D>
__global__ void k_gat(const float* __restrict__ fs, const float* __restrict__ fd,
                      const float* __restrict__ attn, float* __restrict__ hout) {
    constexpr int VPT = D / 32;
    constexpr int HD = NH * D;
    __shared__ float sh[NH][D];
    const int lane = threadIdx.x & 31;
    const int h = threadIdx.x >> 5;

    float areg[VPT];
#pragma unroll
    for (int i = 0; i < VPT; i++) areg[i] = attn[h * D + i * 32 + lane];

    for (int v = blockIdx.x; v < NN; v += gridDim.x) {
        float fdr[VPT];
        const float* fdp = fd + (long)v * HD + h * D;
#pragma unroll
        for (int i = 0; i < VPT; i++) fdr[i] = fdp[i * 32 + lane];

        const int s0 = g_rs[v], s1 = g_rs[v + 1];
        float m = -INF_, ssum = 0.f;
        float acc[VPT];
#pragma unroll
        for (int i = 0; i < VPT; i++) acc[i] = 0.f;

        for (int idx = s0; idx < s1; idx++) {
            int u = g_adj[idx];
            const float* fsp = fs + (long)u * HD + h * D;
            float fu[VPT];
            float p = 0.f;
#pragma unroll
            for (int i = 0; i < VPT; i++) {
                fu[i] = fsp[i * 32 + lane];
                float t = fu[i] + fdr[i];
                t = t > 0.f ? t : SLOPE * t;
                p += areg[i] * t;
            }
#pragma unroll
            for (int o = 16; o; o >>= 1) p += __shfl_xor_sync(0xffffffffu, p, o);
            float mn = fmaxf(m, p);
            float sc = __expf(m - mn);       // first iter: exp(-inf) = 0
            float pe = __expf(p - mn);
            ssum = ssum * sc + pe;
#pragma unroll
            for (int i = 0; i < VPT; i++) acc[i] = acc[i] * sc + pe * fu[i];
            m = mn;
        }
        float inv = (s1 > s0) ? 1.f / ssum : 0.f;
#pragma unroll
        for (int i = 0; i < VPT; i++) sh[h][i * 32 + lane] = acc[i] * inv;
        __syncthreads();
        for (int d = threadIdx.x; d < D; d += blockDim.x) {
            float mx = fmaxf(fmaxf(sh[0][d], sh[1][d]), fmaxf(sh[2][d], sh[3][d]));
            hout[(long)v * D + d] = mx;
        }
        __syncthreads();
    }
}

// ---------------- global attention pooling: one block (128 thr) per graph ----------------
__global__ void k_pool(const float* __restrict__ gw, const float* __restrict__ gb,
                       float* __restrict__ out, int npg) {
    const int g = blockIdx.x;
    const int tid = threadIdx.x;
    const int lane = tid & 31;
    const int w = tid >> 5;
    extern __shared__ float sg[];        // npg floats
    __shared__ float red[16];
    const int base = g * npg;

    float gwr[4];
#pragma unroll
    for (int i = 0; i < 4; i++) gwr[i] = gw[i * 32 + lane];
    const float gbv = gb[0];

    // phase 1: gate per node (warp per node)
    for (int v = w; v < npg; v += 4) {
        const float* hp = g_h2 + (long)(base + v) * H2D;
        float p = 0.f;
#pragma unroll
        for (int i = 0; i < 4; i++) p += gwr[i] * hp[i * 32 + lane];
#pragma unroll
        for (int o = 16; o; o >>= 1) p += __shfl_xor_sync(0xffffffffu, p, o);
        if (lane == 0) sg[v] = p + gbv;
    }
    __syncthreads();

    // phase 2: softmax over graph
    float mx = -INF_;
    for (int v = tid; v < npg; v += 128) mx = fmaxf(mx, sg[v]);
#pragma unroll
    for (int o = 16; o; o >>= 1) mx = fmaxf(mx, __shfl_xor_sync(0xffffffffu, mx, o));
    if (lane == 0) red[w] = mx;
    __syncthreads();
    if (tid == 0) red[8] = fmaxf(fmaxf(red[0], red[1]), fmaxf(red[2], red[3]));
    __syncthreads();
    const float M = red[8];

    float ss = 0.f;
    for (int v = tid; v < npg; v += 128) {
        float e = __expf(sg[v] - M);
        sg[v] = e;
        ss += e;
    }
#pragma unroll
    for (int o = 16; o; o >>= 1) ss += __shfl_xor_sync(0xffffffffu, ss, o);
    if (lane == 0) red[w] = ss;
    __syncthreads();
    if (tid == 0) red[9] = red[0] + red[1] + red[2] + red[3];
    __syncthreads();
    const float inv = 1.f / red[9];

    // phase 3: weighted sum over nodes, thread = output dim
    float accD = 0.f;
    for (int v = 0; v < npg; v++)
        accD += sg[v] * g_h2[(long)(base + v) * H2D + tid];
    out[g * H2D + tid] = accD * inv;
}

// ---------------- launch ----------------
extern "C" void kernel_launch(void* const* d_in, const int* in_sizes, int n_in,
                              void* d_out, int out_size) {
    const float* x    = (const float*)d_in[0];
    const int* esrc   = (const int*)d_in[1];
    const int* edst   = (const int*)d_in[2];
    // d_in[3] = node_graph (implied by contiguous blocks; unused)
    const float* Wl1  = (const float*)d_in[4];
    const float* bl1  = (const float*)d_in[5];
    const float* Wr1  = (const float*)d_in[6];
    const float* br1  = (const float*)d_in[7];
    const float* at1  = (const float*)d_in[8];
    const float* Wl2  = (const float*)d_in[9];
    const float* bl2  = (const float*)d_in[10];
    const float* Wr2  = (const float*)d_in[11];
    const float* br2  = (const float*)d_in[12];
    const float* at2  = (const float*)d_in[13];
    const float* gw   = (const float*)d_in[14];
    const float* gb   = (const float*)d_in[15];

    const int E = in_sizes[1];
    const int N = in_sizes[0] / 128;
    const int G = out_size / H2D;
    const int npg = N / G;

    float* fs1; float* fd1; float* h1; float* fs2; float* fd2; float* h2;
    cudaGetSymbolAddress((void**)&fs1, g_fs1);
    cudaGetSymbolAddress((void**)&fd1, g_fd1);
    cudaGetSymbolAddress((void**)&h1,  g_h1);
    cudaGetSymbolAddress((void**)&fs2, g_fs2);
    cudaGetSymbolAddress((void**)&fd2, g_fd2);
    cudaGetSymbolAddress((void**)&h2,  g_h2);

    // ---- CSR build (deterministic) ----
    k_zero_deg<<<(NN + 255) / 256, 256>>>();
    k_hist<<<(E + 255) / 256, 256>>>(edst, E);
    k_scan<<<1, 1024>>>(E);
    k_scatter<<<(E + 255) / 256, 256>>>(edst, E);
    k_sortseg<<<(NN + 255) / 256, 256>>>();
    k_eid2src<<<(E + 255) / 256, 256>>>(esrc, E);

    const int rowBlocks = (N + 127) / 128;

    // ---- layer 1: fs1/fd1 in one dual GEMM ----
    {
        dim3 grid(2 * (NH * H1D / 128), rowBlocks);
        k_sgemm_dual<<<grid, 256>>>(x, Wl1, bl1, fs1, Wr1, br1, fd1, N, 128, NH * H1D);
    }
    k_gat<H1D><<<2368, 128>>>(fs1, fd1, at1, h1);

    // ---- layer 2 ----
    {
        dim3 grid(2 * (NH * H2D / 128), rowBlocks);
        k_sgemm_dual<<<grid, 256>>>(h1, Wl2, bl2, fs2, Wr2, br2, fd2, N, H1D, NH * H2D);
    }
    k_gat<H2D><<<2368, 128>>>(fs2, fd2, at2, h2);

    // ---- pooling ----
    k_pool<<<G, 128, npg * sizeof(float)>>>(gw, gb, (float*)d_out, npg);
}

// round 4
// speedup vs baseline: 1.0642x; 1.0474x over previous
#include <cuda_runtime.h>
#include <cuda_bf16.h>
#include <math.h>
#include <stdint.h>

// ---------------- problem constants (fixed by the dataset) ----------------
#define NN   50000      // nodes
#define EE   500000     // edges
#define GG   50         // graphs
#define INF_ 3.402823466e+38f

#define H1D  64         // HID[0]
#define H2D  128        // HID[1]
#define NH   4          // heads
#define SLOPE 0.2f

// ---------------- scratch (device globals; no allocation) ----------------
__device__ float g_fs1[NN * NH * H1D];
__device__ float g_fd1[NN * NH * H1D];
__device__ float g_h1 [NN * H1D];
__device__ float g_fs2[NN * NH * H2D];
__device__ float g_fd2[NN * NH * H2D];
__device__ float g_h2 [NN * H2D];

__device__ int g_deg[NN];
__device__ int g_rs [NN + 1];
__device__ int g_cur[NN];
__device__ int g_adj[EE];       // dst-sorted src list (CSR payload)

// ---------------- CSR build ----------------
__global__ void k_zero_deg() {
    int i = blockIdx.x * blockDim.x + threadIdx.x;
    if (i < NN) g_deg[i] = 0;
}

__global__ void k_hist(const int* __restrict__ dst, int E) {
    int i = blockIdx.x * blockDim.x + threadIdx.x;
    if (i < E) atomicAdd(&g_deg[dst[i]], 1);
}

__global__ void k_scan(int E) {
    __shared__ int sm[1024];
    int tid = threadIdx.x;
    const int chunk = (NN + 1023) / 1024;
    int b = tid * chunk;
    int e = b + chunk; if (e > NN) e = NN;
    int s = 0;
    for (int i = b; i < e; i++) s += g_deg[i];
    sm[tid] = s;
    __syncthreads();
    for (int off = 1; off < 1024; off <<= 1) {
        int v = (tid >= off) ? sm[tid - off] : 0;
        __syncthreads();
        sm[tid] += v;
        __syncthreads();
    }
    int run = sm[tid] - s;   // exclusive prefix for this chunk
    for (int i = b; i < e; i++) {
        g_rs[i] = run;
        g_cur[i] = run;
        run += g_deg[i];
    }
    if (tid == 0) g_rs[NN] = E;
}

__global__ void k_scatter(const int* __restrict__ dst, int E) {
    int i = blockIdx.x * blockDim.x + threadIdx.x;
    if (i < E) {
        int p = atomicAdd(&g_cur[dst[i]], 1);
        g_adj[p] = i;                 // edge id; sorted next for determinism
    }
}

__global__ void k_sortseg() {        // per-node insertion sort -> deterministic order
    int v = blockIdx.x * blockDim.x + threadIdx.x;
    if (v >= NN) return;
    int s = g_rs[v], e = g_rs[v + 1];
    for (int i = s + 1; i < e; i++) {
        int key = g_adj[i];
        int j = i - 1;
        while (j >= s && g_adj[j] > key) { g_adj[j + 1] = g_adj[j]; j--; }
        g_adj[j + 1] = key;
    }
}

__global__ void k_eid2src(const int* __restrict__ src, int E) {
    int i = blockIdx.x * blockDim.x + threadIdx.x;
    if (i < E) g_adj[i] = src[g_adj[i]];
}

// ---------------- tf32 split helpers ----------------
__device__ __forceinline__ uint32_t f2tf32(float x) {
    uint32_t r;
    asm("cvt.rna.tf32.f32 %0, %1;" : "=r"(r) : "f"(x));
    return r;
}
__device__ __forceinline__ void split_tf32(float x, uint32_t& hi, uint32_t& lo) {
    hi = f2tf32(x);
    float hf = __uint_as_float(hi);
    lo = f2tf32(x - hf);
}
__device__ __forceinline__ void mma_tf32(float c[4],
                                         uint32_t a0, uint32_t a1, uint32_t a2, uint32_t a3,
                                         uint32_t b0, uint32_t b1) {
    asm("mma.sync.aligned.m16n8k8.row.col.f32.tf32.tf32.f32 "
        "{%0,%1,%2,%3}, {%4,%5,%6,%7}, {%8,%9}, {%0,%1,%2,%3};"
        : "+f"(c[0]), "+f"(c[1]), "+f"(c[2]), "+f"(c[3])
        : "r"(a0), "r"(a1), "r"(a2), "r"(a3), "r"(b0), "r"(b1));
}

// ---------------- dual-output tf32 tensor-core GEMM + bias ----------------
// C1[N,M] = A[N,K] @ B1[K,M] + b1 ; C2 likewise (grid.x split).
// Block tile 128x128, BK=32, 256 threads (8 warps: 4x2 of 32x64 warp tiles).
// 3-pass compensated tf32: C = Ah*Bh + Al*Bh + Ah*Bl (~fp32 accuracy).
__global__ __launch_bounds__(256)
void k_gemm_tf32_dual(const float* __restrict__ A,
                      const float* __restrict__ B1, const float* __restrict__ b1, float* __restrict__ C1,
                      const float* __restrict__ B2, const float* __restrict__ b2, float* __restrict__ C2,
                      int Nrows, int K, int M) {
    const int nbx = M >> 7;
    int bx = blockIdx.x;
    const float* B = B1; const float* bias = b1; float* C = C1;
    if (bx >= nbx) { bx -= nbx; B = B2; bias = b2; C = C2; }
    const int row0 = blockIdx.y << 7;
    const int col0 = bx << 7;

    __shared__ float As[128][36];   // [m][k], stride 36 -> conflict-free frags
    __shared__ float Bs[32][136];   // [k][n], stride 136 -> conflict-free frags

    const int tid = threadIdx.x;
    const int lane = tid & 31;
    const int wid = tid >> 5;
    const int wm = wid & 3;          // 0..3 -> 32 rows each
    const int wn = wid >> 2;         // 0..1 -> 64 cols each
    const int g = lane >> 2;         // 0..7
    const int t = lane & 3;          // 0..3

    float acc[2][8][4];
#pragma unroll
    for (int i = 0; i < 2; i++)
#pragma unroll
        for (int j = 0; j < 8; j++)
#pragma unroll
            for (int q = 0; q < 4; q++) acc[i][j][q] = 0.f;

    const int ktiles = K >> 5;
    for (int kt = 0; kt < ktiles; kt++) {
        const int kk = kt << 5;
        // load A tile 128x32 (guarded), B tile 32x128
#pragma unroll
        for (int i = 0; i < 4; i++) {
            int f = tid + i * 256;
            int row = f >> 3, kg = f & 7;
            float4 v = make_float4(0.f, 0.f, 0.f, 0.f);
            if (row0 + row < Nrows)
                v = *(const float4*)(A + (long)(row0 + row) * K + kk + kg * 4);
            *(float4*)&As[row][kg * 4] = v;
        }
#pragma unroll
        for (int i = 0; i < 4; i++) {
            int f = tid + i * 256;
            int kr = f >> 5, ng = f & 31;
            float4 v = *(const float4*)(B + (long)(kk + kr) * M + col0 + ng * 4);
            *(float4*)&Bs[kr][ng * 4] = v;
        }
        __syncthreads();

#pragma unroll
        for (int k8 = 0; k8 < 4; k8++) {
            const int k0 = k8 * 8;
            uint32_t Ah[2][4], Al[2][4];
#pragma unroll
            for (int mt = 0; mt < 2; mt++) {
                const int mr = wm * 32 + mt * 16 + g;
                float a0 = As[mr][k0 + t];
                float a1 = As[mr + 8][k0 + t];
                float a2 = As[mr][k0 + t + 4];
                float a3 = As[mr + 8][k0 + t + 4];
                split_tf32(a0, Ah[mt][0], Al[mt][0]);
                split_tf32(a1, Ah[mt][1], Al[mt][1]);
                split_tf32(a2, Ah[mt][2], Al[mt][2]);
                split_tf32(a3, Ah[mt][3], Al[mt][3]);
            }
#pragma unroll
            for (int nt = 0; nt < 8; nt++) {
                const int nc = wn * 64 + nt * 8 + g;
                float b0f = Bs[k0 + t][nc];
                float b1f = Bs[k0 + t + 4][nc];
                uint32_t bh0, bl0, bh1, bl1;
                split_tf32(b0f, bh0, bl0);
                split_tf32(b1f, bh1, bl1);
#pragma unroll
                for (int mt = 0; mt < 2; mt++) {
                    mma_tf32(acc[mt][nt], Ah[mt][0], Ah[mt][1], Ah[mt][2], Ah[mt][3], bh0, bh1);
                    mma_tf32(acc[mt][nt], Al[mt][0], Al[mt][1], Al[mt][2], Al[mt][3], bh0, bh1);
                    mma_tf32(acc[mt][nt], Ah[mt][0], Ah[mt][1], Ah[mt][2], Ah[mt][3], bl0, bl1);
                }
            }
        }
        __syncthreads();
    }

    // epilogue: bias + guarded float2 stores
#pragma unroll
    for (int nt = 0; nt < 8; nt++) {
        const int c = col0 + wn * 64 + nt * 8 + t * 2;
        const float2 bv = *(const float2*)(bias + c);
#pragma unroll
        for (int mt = 0; mt < 2; mt++) {
            const int r0 = row0 + wm * 32 + mt * 16 + g;
            if (r0 < Nrows) {
                float2 o; o.x = acc[mt][nt][0] + bv.x; o.y = acc[mt][nt][1] + bv.y;
                *(float2*)(C + (long)r0 * M + c) = o;
            }
            if (r0 + 8 < Nrows) {
                float2 o; o.x = acc[mt][nt][2] + bv.x; o.y = acc[mt][nt][3] + bv.y;
                *(float2*)(C + (long)(r0 + 8) * M + c) = o;
            }
        }
    }
}

// ---------------- fused GATv2 edge-softmax + aggregate + head-maxpool ----------------
// block = 128 threads = 4 warps = 4 heads; grid-stride over nodes
template <int D>
__global__ void k_gat(const float* __restrict__ fs, const float* __restrict__ fd,
                      const float* __restrict__ attn, float* __restrict__ hout) {
    constexpr int VPT = D / 32;
    constexpr int HD = NH * D;
    __shared__ float sh[NH][D];
    const int lane = threadIdx.x & 31;
    const int h = threadIdx.x >> 5;

    float areg[VPT];
#pragma unroll
    for (int i = 0; i < VPT; i++) areg[i] = attn[h * D + i * 32 + lane];

    for (int v = blockIdx.x; v < NN; v += gridDim.x) {
        float fdr[VPT];
        const float* fdp = fd + (long)v * HD + h * D;
#pragma unroll
        for (int i = 0; i < VPT; i++) fdr[i] = fdp[i * 32 + lane];

        const int s0 = g_rs[v], s1 = g_rs[v + 1];
        float m = -INF_, ssum = 0.f;
        float acc[VPT];
#pragma unroll
        for (int i = 0; i < VPT; i++) acc[i] = 0.f;

        for (int idx = s0; idx < s1; idx++) {
            int u = g_adj[idx];
            const float* fsp = fs + (long)u * HD + h * D;
            float fu[VPT];
            float p = 0.f;
#pragma unroll
            for (int i = 0; i < VPT; i++) {
                fu[i] = fsp[i * 32 + lane];
                float t = fu[i] + fdr[i];
                t = t > 0.f ? t : SLOPE * t;
                p += areg[i] * t;
            }
#pragma unroll
            for (int o = 16; o; o >>= 1) p += __shfl_xor_sync(0xffffffffu, p, o);
            float mn = fmaxf(m, p);
            float sc = __expf(m - mn);       // first iter: exp(-inf) = 0
            float pe = __expf(p - mn);
            ssum = ssum * sc + pe;
#pragma unroll
            for (int i = 0; i < VPT; i++) acc[i] = acc[i] * sc + pe * fu[i];
            m = mn;
        }
        float inv = (s1 > s0) ? 1.f / ssum : 0.f;
#pragma unroll
        for (int i = 0; i < VPT; i++) sh[h][i * 32 + lane] = acc[i] * inv;
        __syncthreads();
        for (int d = threadIdx.x; d < D; d += blockDim.x) {
            float mx = fmaxf(fmaxf(sh[0][d], sh[1][d]), fmaxf(sh[2][d], sh[3][d]));
            hout[(long)v * D + d] = mx;
        }
        __syncthreads();
    }
}

// ---------------- global attention pooling: one block (128 thr) per graph ----------------
__global__ void k_pool(const float* __restrict__ gw, const float* __restrict__ gb,
                       float* __restrict__ out, int npg) {
    const int g = blockIdx.x;
    const int tid = threadIdx.x;
    const int lane = tid & 31;
    const int w = tid >> 5;
    extern __shared__ float sg[];        // npg floats
    __shared__ float red[16];
    const int base = g * npg;

    float gwr[4];
#pragma unroll
    for (int i = 0; i < 4; i++) gwr[i] = gw[i * 32 + lane];
    const float gbv = gb[0];

    for (int v = w; v < npg; v += 4) {
        const float* hp = g_h2 + (long)(base + v) * H2D;
        float p = 0.f;
#pragma unroll
        for (int i = 0; i < 4; i++) p += gwr[i] * hp[i * 32 + lane];
#pragma unroll
        for (int o = 16; o; o >>= 1) p += __shfl_xor_sync(0xffffffffu, p, o);
        if (lane == 0) sg[v] = p + gbv;
    }
    __syncthreads();

    float mx = -INF_;
    for (int v = tid; v < npg; v += 128) mx = fmaxf(mx, sg[v]);
#pragma unroll
    for (int o = 16; o; o >>= 1) mx = fmaxf(mx, __shfl_xor_sync(0xffffffffu, mx, o));
    if (lane == 0) red[w] = mx;
    __syncthreads();
    if (tid == 0) red[8] = fmaxf(fmaxf(red[0], red[1]), fmaxf(red[2], red[3]));
    __syncthreads();
    const float M = red[8];

    float ss = 0.f;
    for (int v = tid; v < npg; v += 128) {
        float e = __expf(sg[v] - M);
        sg[v] = e;
        ss += e;
    }
#pragma unroll
    for (int o = 16; o; o >>= 1) ss += __shfl_xor_sync(0xffffffffu, ss, o);
    if (lane == 0) red[w] = ss;
    __syncthreads();
    if (tid == 0) red[9] = red[0] + red[1] + red[2] + red[3];
    __syncthreads();
    const float inv = 1.f / red[9];

    float accD = 0.f;
    for (int v = 0; v < npg; v++)
        accD += sg[v] * g_h2[(long)(base + v) * H2D + tid];
    out[g * H2D + tid] = accD * inv;
}

// ---------------- launch ----------------
extern "C" void kernel_launch(void* const* d_in, const int* in_sizes, int n_in,
                              void* d_out, int out_size) {
    const float* x    = (const float*)d_in[0];
    const int* esrc   = (const int*)d_in[1];
    const int* edst   = (const int*)d_in[2];
    // d_in[3] = node_graph (contiguous blocks; unused)
    const float* Wl1  = (const float*)d_in[4];
    const float* bl1  = (const float*)d_in[5];
    const float* Wr1  = (const float*)d_in[6];
    const float* br1  = (const float*)d_in[7];
    const float* at1  = (const float*)d_in[8];
    const float* Wl2  = (const float*)d_in[9];
    const float* bl2  = (const float*)d_in[10];
    const float* Wr2  = (const float*)d_in[11];
    const float* br2  = (const float*)d_in[12];
    const float* at2  = (const float*)d_in[13];
    const float* gw   = (const float*)d_in[14];
    const float* gb   = (const float*)d_in[15];

    const int E = in_sizes[1];
    const int N = in_sizes[0] / 128;
    const int G = out_size / H2D;
    const int npg = N / G;

    float* fs1; float* fd1; float* h1; float* fs2; float* fd2; float* h2;
    cudaGetSymbolAddress((void**)&fs1, g_fs1);
    cudaGetSymbolAddress((void**)&fd1, g_fd1);
    cudaGetSymbolAddress((void**)&h1,  g_h1);
    cudaGetSymbolAddress((void**)&fs2, g_fs2);
    cudaGetSymbolAddress((void**)&fd2, g_fd2);
    cudaGetSymbolAddress((void**)&h2,  g_h2);

    // ---- CSR build (deterministic) ----
    k_zero_deg<<<(NN + 255) / 256, 256>>>();
    k_hist<<<(E + 255) / 256, 256>>>(edst, E);
    k_scan<<<1, 1024>>>(E);
    k_scatter<<<(E + 255) / 256, 256>>>(edst, E);
    k_sortseg<<<(NN + 255) / 256, 256>>>();
    k_eid2src<<<(E + 255) / 256, 256>>>(esrc, E);

    const int rowBlocks = (N + 127) / 128;

    // ---- layer 1: fs1/fd1 in one dual tensor GEMM ----
    {
        dim3 grid(2 * (NH * H1D / 128), rowBlocks);
        k_gemm_tf32_dual<<<grid, 256>>>(x, Wl1, bl1, fs1, Wr1, br1, fd1, N, 128, NH * H1D);
    }
    k_gat<H1D><<<2368, 128>>>(fs1, fd1, at1, h1);

    // ---- layer 2 ----
    {
        dim3 grid(2 * (NH * H2D / 128), rowBlocks);
        k_gemm_tf32_dual<<<grid, 256>>>(h1, Wl2, bl2, fs2, Wr2, br2, fd2, N, H1D, NH * H2D);
    }
    k_gat<H2D><<<2368, 128>>>(fs2, fd2, at2, h2);

    // ---- pooling ----
    k_pool<<<G, 128, npg * sizeof(float)>>>(gw, gb, (float*)d_out, npg);
}